// round 16
// baseline (speedup 1.0000x reference)
#include <cuda_runtime.h>

#define BN   4
#define NF   8
#define CC   8
#define NPIX (512 * 512)
#define NG   (NPIX / 4)
#define P2_BX  128
#define P2_THR 256
#define P2_TOTAL (P2_BX * BN)

struct Scratch {
    float sums[BN][CC][NF];   // 256
    float counts[BN][CC];     // 32
    float dist[BN];           // 4
    unsigned int ticket;
};
__device__ Scratch g_s;   // zero-init at module load; self-reset every run

__device__ __forceinline__ unsigned long long ffma2(unsigned long long a,
                                                    unsigned long long b,
                                                    unsigned long long c) {
    unsigned long long d;
    asm("fma.rn.f32x2 %0, %1, %2, %3;" : "=l"(d) : "l"(a), "l"(b), "l"(c));
    return d;
}
__device__ __forceinline__ unsigned long long fadd2(unsigned long long a,
                                                    unsigned long long b) {
    unsigned long long d;
    asm("add.rn.f32x2 %0, %1, %2;" : "=l"(d) : "l"(a), "l"(b));
    return d;
}
__device__ __forceinline__ unsigned long long pack2(float lo, float hi) {
    unsigned long long r;
    asm("mov.b64 %0, {%1, %2};" : "=l"(r) : "f"(lo), "f"(hi));
    return r;
}
__device__ __forceinline__ void unpack2(unsigned long long v, float& lo, float& hi) {
    asm("mov.b64 {%0, %1}, %2;" : "=f"(lo), "=f"(hi) : "l"(v));
}
__device__ __forceinline__ float f4get(const float4 v, int i) {
    return i == 0 ? v.x : i == 1 ? v.y : i == 2 ? v.z : v.w;
}
__device__ __forceinline__ int i4get(const int4 v, int i) {
    return i == 0 ? v.x : i == 1 ? v.y : i == 2 ? v.z : v.w;
}

// ---------------------------------------------------------------------------
// Pass 1 (exact R2/R15): per-cluster counts + feature sums.
// ---------------------------------------------------------------------------
__global__ void __launch_bounds__(128) k_pass1(const float* __restrict__ pred,
                                               const int* __restrict__ tgt) {
    const int b = blockIdx.y;
    const float4* p = (const float4*)(pred + (size_t)b * NF * NPIX);
    const int4*   g = (const int4*)(tgt + (size_t)b * NPIX);
    const unsigned long long ONE2 = 0x3F8000003F800000ull;

    unsigned long long acc[CC][4];
    int icnt[CC];
#pragma unroll
    for (int c = 0; c < CC; c++) {
        icnt[c] = 0;
#pragma unroll
        for (int k = 0; k < 4; k++) acc[c][k] = 0ull;
    }

    for (int n = blockIdx.x * blockDim.x + threadIdx.x; n < NG;
         n += gridDim.x * blockDim.x) {
        int4 lab4 = g[n];
        float4 v[NF];
#pragma unroll
        for (int f = 0; f < NF; f++) v[f] = p[f * (NPIX / 4) + n];

#pragma unroll
        for (int px = 0; px < 4; px++) {
            int lab = i4get(lab4, px);
            unsigned long long pr[4];
#pragma unroll
            for (int k = 0; k < 4; k++)
                pr[k] = pack2(f4get(v[2 * k], px), f4get(v[2 * k + 1], px));
#pragma unroll
            for (int c = 0; c < CC; c++) {
                bool hit = (lab == c);
                unsigned long long m2 = hit ? ONE2 : 0ull;
                icnt[c] += hit;
#pragma unroll
                for (int k = 0; k < 4; k++) acc[c][k] = ffma2(m2, pr[k], acc[c][k]);
            }
        }
    }

#pragma unroll
    for (int c = 0; c < CC; c++) {
#pragma unroll
        for (int k = 0; k < 4; k++) {
            unsigned long long x = acc[c][k];
#pragma unroll
            for (int o = 16; o > 0; o >>= 1)
                x = fadd2(x, __shfl_down_sync(0xffffffffu, x, o));
            acc[c][k] = x;
        }
        int ic = icnt[c];
#pragma unroll
        for (int o = 16; o > 0; o >>= 1) ic += __shfl_down_sync(0xffffffffu, ic, o);
        icnt[c] = ic;
    }

    __shared__ float sw[4][72];
    int tid = threadIdx.x, wid = tid >> 5, lane = tid & 31;
    if (lane == 0) {
#pragma unroll
        for (int c = 0; c < CC; c++) {
#pragma unroll
            for (int k = 0; k < 4; k++) {
                float lo, hi;
                unpack2(acc[c][k], lo, hi);
                sw[wid][c * NF + 2 * k]     = lo;
                sw[wid][c * NF + 2 * k + 1] = hi;
            }
            sw[wid][64 + c] = (float)icnt[c];
        }
    }
    __syncthreads();
    if (tid < 72) {
        float s = sw[0][tid] + sw[1][tid] + sw[2][tid] + sw[3][tid];
        if (tid < 64)
            atomicAdd(&((float*)g_s.sums)[b * 64 + tid], s);
        else
            atomicAdd(&g_s.counts[b][tid - 64], s);
    }
}

// ---------------------------------------------------------------------------
// Pass 2: two pixel-groups per thread, all 18 LDG.128 issued up front (MLP x2),
// then hinge compute; fused finalize + scratch self-reset (verified R15).
// ---------------------------------------------------------------------------
__global__ void __launch_bounds__(P2_THR) k_pass2(const float* __restrict__ pred,
                                                  const int* __restrict__ tgt,
                                                  float* __restrict__ out) {
    const int b = blockIdx.y;
    __shared__ float smean[NF][CC];
    int tid = threadIdx.x;
    if (tid < 64) {
        int c = tid & 7, f = tid >> 3;
        smean[f][c] = g_s.sums[b][c][f] / g_s.counts[b][c];
    }
    __syncthreads();

    const float4* p = (const float4*)(pred + (size_t)b * NF * NPIX);
    const int4*   g = (const int4*)(tgt + (size_t)b * NPIX);

    // two groups per thread: n0 and n1 = n0 + P2_THR (coalesced both times)
    const int n0 = blockIdx.x * (2 * P2_THR) + tid;
    const int n1 = n0 + P2_THR;

    int4 lab0 = g[n0];
    int4 lab1 = g[n1];
    float4 v0[NF], v1[NF];
#pragma unroll
    for (int f = 0; f < NF; f++) v0[f] = p[f * NG + n0];
#pragma unroll
    for (int f = 0; f < NF; f++) v1[f] = p[f * NG + n1];

    float local = 0.f;
#pragma unroll
    for (int grp = 0; grp < 2; grp++) {
        int4 lab4 = grp ? lab1 : lab0;
        const float4* v = grp ? v1 : v0;
#pragma unroll
        for (int px = 0; px < 4; px++) {
            int lab = i4get(lab4, px);
            float d2 = 0.f;
#pragma unroll
            for (int f = 0; f < NF; f++) {
                float d = smean[f][lab] - f4get(v[f], px);
                d2 = fmaf(d, d, d2);
            }
            float t = sqrtf(d2) - 0.5f;           // DELTA_V
            t = fminf(fmaxf(t, 0.f), 100000.f);
            local = fmaf(t, t, local);
        }
    }

#pragma unroll
    for (int o = 16; o > 0; o >>= 1)
        local += __shfl_down_sync(0xffffffffu, local, o);
    __shared__ float sred[8];
    if ((tid & 31) == 0) sred[tid >> 5] = local;
    __syncthreads();
    if (tid == 0) {
        float s = 0.f;
#pragma unroll
        for (int w = 0; w < 8; w++) s += sred[w];
        atomicAdd(&g_s.dist[b], s);
    }

    // ---- last-block finalize ----
    __shared__ bool s_last;
    __threadfence();
    if (tid == 0) {
        unsigned int t = atomicAdd(&g_s.ticket, 1u);
        s_last = (t == P2_TOTAL - 1);
    }
    __syncthreads();
    if (!s_last) return;

    __shared__ float smu[BN][CC][NF];
    __shared__ float s_ldist[BN], s_lreg[BN], s_inv[BN];
    float cnt_cache = 1.f;
    {
        int bb = tid >> 6, i = (tid >> 3) & 7, j = tid & 7;
        cnt_cache = __ldcg(&g_s.counts[bb][i]);
        smu[bb][i][j] = __ldcg(&g_s.sums[bb][i][j]) / cnt_cache;
    }
    if (tid < BN) { s_ldist[tid] = 0.f; s_lreg[tid] = 0.f; s_inv[tid] = 0.f; }
    __syncthreads();

    {
        int bb = tid >> 6, i = (tid >> 3) & 7, j = tid & 7;
        if (i != j) {
            float d2 = 0.f;
#pragma unroll
            for (int f = 0; f < NF; f++) {
                float d = smu[bb][i][f] - smu[bb][j][f];
                d2 = fmaf(d, d, d2);
            }
            float t = 3.0f - sqrtf(d2);           // 2 * DELTA_D
            t = fminf(fmaxf(t, 0.f), 100000.f);
            atomicAdd(&s_ldist[bb], t * t);
        } else {
            float d2 = 0.f;
#pragma unroll
            for (int f = 0; f < NF; f++)
                d2 = fmaf(smu[bb][i][f], smu[bb][i][f], d2);
            atomicAdd(&s_lreg[bb], sqrtf(d2));
            atomicAdd(&s_inv[bb], 1.0f / cnt_cache);
        }
    }
    __syncthreads();

    if (tid == 0) {
        float total = 0.f;
#pragma unroll
        for (int q = 0; q < BN; q++) {
            float dq = __ldcg(&g_s.dist[q]);
            float l_var  = dq * s_inv[q] / (float)CC;
            float l_dist = s_ldist[q] / (float)(CC * (CC - 1));
            float l_reg  = s_lreg[q] / (float)CC;
            total += l_var + l_dist + 0.001f * l_reg;
        }
        out[0] = total / (float)BN;
    }
    __syncthreads();

    // ---- scratch self-reset for the next graph replay ----
    {
        float* sc = (float*)&g_s;
        sc[tid] = 0.f;                     // sums[0..255]
        if (tid < 36) sc[256 + tid] = 0.f; // counts(32) + dist(4)
        if (tid == 0) g_s.ticket = 0u;
    }
}

extern "C" void kernel_launch(void* const* d_in, const int* in_sizes, int n_in,
                              void* d_out, int out_size) {
    const float* pred = (const float*)d_in[0];
    const int*   tgt  = (const int*)d_in[1];
    float*       out  = (float*)d_out;
    (void)in_sizes; (void)n_in; (void)out_size;

    dim3 grid1(256, BN);
    k_pass1<<<grid1, 128>>>(pred, tgt);
    dim3 grid2(P2_BX, BN);
    k_pass2<<<grid2, P2_THR>>>(pred, tgt, out);
}